// round 3
// baseline (speedup 1.0000x reference)
#include <cuda_runtime.h>
#include <cstdint>

// Problem dims (fixed by the dataset)
#define NN   4096   // nodes
#define EE   8192   // edges
#define INV  512
#define OUTV 512
#define INE  128

// Scratch (allocation-free rule: __device__ globals)
__device__ float g_escale[EE];
__device__ float g_C[(size_t)NN * NN];    // 64 MB: fused 0.5*(M+1)*adj_v
__device__ float g_X[(size_t)NN * OUTV];  // 8 MB: C @ H_v

// ---------------------------------------------------------------------------
// e_scale[e] = sum_k H_e[e,k] * p[k]   (one warp per edge row)
// ---------------------------------------------------------------------------
__global__ void escale_kernel(const float* __restrict__ He,
                              const float* __restrict__ p) {
    int idx  = blockIdx.x * blockDim.x + threadIdx.x;
    int warp = idx >> 5;
    int lane = idx & 31;
    if (warp >= EE) return;
    float4 v  = reinterpret_cast<const float4*>(He + (size_t)warp * INE)[lane];
    float4 pv = reinterpret_cast<const float4*>(p)[lane];
    float s = v.x * pv.x + v.y * pv.y + v.z * pv.z + v.w * pv.w;
#pragma unroll
    for (int o = 16; o; o >>= 1) s += __shfl_xor_sync(0xFFFFFFFFu, s, o);
    if (lane == 0) g_escale[warp] = s;
}

// ---------------------------------------------------------------------------
// Symmetric GEMM with fused epilogue:
//   M[i,j] = sum_k T[i,k]*s[k]*T[j,k]    (symmetric)
//   g_C[i,j] = (i==j) ? adj_v[i,i] : 0.5f*(M[i,j]+1)*adj_v[i,j]
// Only tiles with bi <= bj are computed; bi<bj tiles also write the mirror.
// 128x128 block tile, BK=16, 8x8 per thread, 256 threads.
// ---------------------------------------------------------------------------
#define BM 128
#define BN 128
#define BK 16
#define TM 8
#define TN 8

__global__ __launch_bounds__(256, 2)
void symgemm_kernel(const float* __restrict__ Tm,
                    const float* __restrict__ adjv) {
    const int bj = blockIdx.x, bi = blockIdx.y;
    if (bi > bj) return;

    __shared__ float As[BK][BM];
    __shared__ float Bs[BK][BN];

    const int tid  = threadIdx.x;
    const int tx   = tid & 15;
    const int ty   = tid >> 4;
    const int lrow = tid >> 2;         // 0..63
    const int lcol = (tid & 3) << 2;   // 0,4,8,12

    const float* Arow = Tm + (size_t)(bi * BM + lrow) * EE + lcol;
    const float* Brow = Tm + (size_t)(bj * BM + lrow) * EE + lcol;

    float acc[TM][TN] = {};

    for (int k0 = 0; k0 < EE; k0 += BK) {
        float4 sv = *reinterpret_cast<const float4*>(g_escale + k0 + lcol);
#pragma unroll
        for (int r = 0; r < 2; r++) {
            float4 a = *reinterpret_cast<const float4*>(Arow + (size_t)(r * 64) * EE + k0);
            float4 b = *reinterpret_cast<const float4*>(Brow + (size_t)(r * 64) * EE + k0);
            int row = lrow + r * 64;
            As[lcol + 0][row] = a.x * sv.x;
            As[lcol + 1][row] = a.y * sv.y;
            As[lcol + 2][row] = a.z * sv.z;
            As[lcol + 3][row] = a.w * sv.w;
            Bs[lcol + 0][row] = b.x;
            Bs[lcol + 1][row] = b.y;
            Bs[lcol + 2][row] = b.z;
            Bs[lcol + 3][row] = b.w;
        }
        __syncthreads();
#pragma unroll
        for (int k = 0; k < BK; k++) {
            float4 a0 = *reinterpret_cast<const float4*>(&As[k][ty * TM]);
            float4 a1 = *reinterpret_cast<const float4*>(&As[k][ty * TM + 4]);
            float4 b0 = *reinterpret_cast<const float4*>(&Bs[k][tx * TN]);
            float4 b1 = *reinterpret_cast<const float4*>(&Bs[k][tx * TN + 4]);
            float af[8] = {a0.x, a0.y, a0.z, a0.w, a1.x, a1.y, a1.z, a1.w};
            float bf[8] = {b0.x, b0.y, b0.z, b0.w, b1.x, b1.y, b1.z, b1.w};
#pragma unroll
            for (int m = 0; m < TM; m++)
#pragma unroll
                for (int n = 0; n < TN; n++)
                    acc[m][n] += af[m] * bf[n];
        }
        __syncthreads();
    }

    // Fused epilogue: g_C = 0.5*(M+1)*adj_v, diagonal = adj_v[i,i]; mirror for bi<bj.
    const int gi0 = bi * BM + ty * TM;
    const int gj0 = bj * BN + tx * TN;
#pragma unroll
    for (int m = 0; m < TM; m++) {
        const int i = gi0 + m;
#pragma unroll
        for (int n = 0; n < TN; n++) {
            const int j = gj0 + n;
            const float Mv = 0.5f * (acc[m][n] + 1.0f);
            g_C[(size_t)i * NN + j] =
                (i == j) ? adjv[(size_t)i * NN + i] : Mv * adjv[(size_t)i * NN + j];
            if (bi != bj)
                g_C[(size_t)j * NN + i] = Mv * adjv[(size_t)j * NN + i];
        }
    }
}

// ---------------------------------------------------------------------------
// Generic SGEMM: Out[M, ldn] = A[M, K] @ B[K, ldn] (+ bias[ldn] if non-null)
// Same 128x128 / BK=16 / 8x8 register tiling.
// ---------------------------------------------------------------------------
__global__ __launch_bounds__(256, 2)
void sgemm_kernel(const float* __restrict__ A, const float* __restrict__ B,
                  float* __restrict__ Out, const float* __restrict__ bias,
                  int K, int ldn) {
    __shared__ float As[BK][BM];
    __shared__ float Bs[BK][BN];

    const int tid  = threadIdx.x;
    const int tx   = tid & 15;
    const int ty   = tid >> 4;
    const int lrow = tid >> 2;          // 0..63 (A tile rows)
    const int lcol = (tid & 3) << 2;    // 0,4,8,12
    const int brow = tid >> 5;          // 0..7  (B tile rows, 2 passes)
    const int bcol = (tid & 31) << 2;   // 0..124

    const float* Aptr = A + (size_t)(blockIdx.y * BM + lrow) * K + lcol;
    const float* Bptr = B + (size_t)brow * ldn + blockIdx.x * BN + bcol;

    float acc[TM][TN] = {};

    for (int k0 = 0; k0 < K; k0 += BK) {
#pragma unroll
        for (int r = 0; r < 2; r++) {
            float4 a = *reinterpret_cast<const float4*>(Aptr + (size_t)(r * 64) * K + k0);
            int row = lrow + r * 64;
            As[lcol + 0][row] = a.x;
            As[lcol + 1][row] = a.y;
            As[lcol + 2][row] = a.z;
            As[lcol + 3][row] = a.w;
            float4 bv = *reinterpret_cast<const float4*>(Bptr + (size_t)(k0 + r * 8) * ldn);
            *reinterpret_cast<float4*>(&Bs[brow + r * 8][bcol]) = bv;
        }
        __syncthreads();
#pragma unroll
        for (int k = 0; k < BK; k++) {
            float4 a0 = *reinterpret_cast<const float4*>(&As[k][ty * TM]);
            float4 a1 = *reinterpret_cast<const float4*>(&As[k][ty * TM + 4]);
            float4 b0 = *reinterpret_cast<const float4*>(&Bs[k][tx * TN]);
            float4 b1 = *reinterpret_cast<const float4*>(&Bs[k][tx * TN + 4]);
            float af[8] = {a0.x, a0.y, a0.z, a0.w, a1.x, a1.y, a1.z, a1.w};
            float bf[8] = {b0.x, b0.y, b0.z, b0.w, b1.x, b1.y, b1.z, b1.w};
#pragma unroll
            for (int m = 0; m < TM; m++)
#pragma unroll
                for (int n = 0; n < TN; n++)
                    acc[m][n] += af[m] * bf[n];
        }
        __syncthreads();
    }

    const int gi0 = blockIdx.y * BM + ty * TM;
    const int gj0 = blockIdx.x * BN + tx * TN;
#pragma unroll
    for (int m = 0; m < TM; m++) {
        const int i = gi0 + m;
#pragma unroll
        for (int n = 0; n < TN; n++) {
            const int j = gj0 + n;
            float v = acc[m][n];
            if (bias) v += bias[j];
            Out[(size_t)i * ldn + j] = v;
        }
    }
}

// ---------------------------------------------------------------------------
// H_e passthrough into the second half of the output
// ---------------------------------------------------------------------------
__global__ void copy_kernel(const float* __restrict__ src, float* __restrict__ dst) {
    int i = blockIdx.x * blockDim.x + threadIdx.x;  // float4 index
    reinterpret_cast<float4*>(dst)[i] = reinterpret_cast<const float4*>(src)[i];
}

// ---------------------------------------------------------------------------
extern "C" void kernel_launch(void* const* d_in, const int* in_sizes, int n_in,
                              void* d_out, int out_size) {
    const float* Hv   = (const float*)d_in[0];   // [4096, 512]
    const float* He   = (const float*)d_in[1];   // [8192, 128]
    // d_in[2] = adj_e : unused by the reference's node_layer path
    const float* adjv = (const float*)d_in[3];   // [4096, 4096]
    const float* Tm   = (const float*)d_in[4];   // [4096, 8192]
    const float* W    = (const float*)d_in[5];   // [512, 512]
    const float* p    = (const float*)d_in[6];   // [1, 128]
    const float* bias = (const float*)d_in[7];   // [512]
    float* out = (float*)d_out;                  // [4096*512] ret ++ [8192*128] H_e

    float *pC = nullptr, *pX = nullptr;
    cudaGetSymbolAddress((void**)&pC, g_C);
    cudaGetSymbolAddress((void**)&pX, g_X);

    // 1) e_scale = H_e @ p^T
    escale_kernel<<<(EE * 32) / 256, 256>>>(He, p);

    // 2) g_C = 0.5*(T diag(s) T^T + 1) * adj_v  (diag -> adj_v[i,i]); symmetric tiles
    symgemm_kernel<<<dim3(NN / BM, NN / BM), 256>>>(Tm, adjv);

    // 3) g_X = g_C @ H_v     [4096, 512], K = 4096
    sgemm_kernel<<<dim3(INV / BN, NN / BM), 256>>>(pC, Hv, pX, nullptr, NN, INV);

    // 4) ret = g_X @ W + bias  [4096, 512], K = 512
    sgemm_kernel<<<dim3(OUTV / BN, NN / BM), 256>>>(pX, W, out, bias, INV, OUTV);

    // 5) append H_e
    copy_kernel<<<(EE * INE / 4) / 256, 256>>>(He, out + (size_t)NN * OUTV);
}

// round 6
// speedup vs baseline: 2.3807x; 2.3807x over previous
#include <cuda_runtime.h>
#include <cuda_bf16.h>
#include <cstdint>

// Problem dims (fixed by the dataset)
#define NN   4096   // nodes
#define EE   8192   // edges
#define INV  512
#define OUTV 512
#define INE  128

// Scratch (allocation-free rule: __device__ globals)
__device__ float g_escale[EE];
__device__ float g_C[(size_t)NN * NN];                 // 64 MB
__device__ float g_X[(size_t)NN * OUTV];               // 8 MB
// bf16 hi/lo split operands: row r, cols [0,8192)=hi, [8192,16384)=lo
__device__ __nv_bfloat16 g_A16[(size_t)NN * 2 * EE];   // 128 MB (scaled by e_scale)
__device__ __nv_bfloat16 g_B16[(size_t)NN * 2 * EE];   // 128 MB (unscaled)

// ============================================================================
// sm_80+ PTX helpers (NO arch-specific 'a' features — target is plain sm_103)
// ============================================================================
__device__ __forceinline__ uint32_t smem_u32(const void* p) {
    uint32_t a;
    asm("{ .reg .u64 t; cvta.to.shared.u64 t, %1; cvt.u32.u64 %0, t; }" : "=r"(a) : "l"(p));
    return a;
}

#define SWZ(o) ((o) ^ (((o) >> 3) & 0x70))

#define CP_ASYNC16(saddr, gptr) \
    asm volatile("cp.async.cg.shared.global [%0], [%1], 16;" \
                 :: "r"(saddr), "l"((size_t)__cvta_generic_to_global((const void*)(gptr))))
#define CP_COMMIT() asm volatile("cp.async.commit_group;" ::: "memory")
#define CP_WAIT(n)  asm volatile("cp.async.wait_group " #n ";" ::: "memory")

#define LDSM_X4(r0, r1, r2, r3, addr) \
    asm volatile("ldmatrix.sync.aligned.m8n8.x4.shared.b16 {%0,%1,%2,%3}, [%4];" \
                 : "=r"(r0), "=r"(r1), "=r"(r2), "=r"(r3) : "r"(addr))

#define MMA16816(d, a, b0, b1) \
    asm volatile("mma.sync.aligned.m16n8k16.row.col.f32.bf16.bf16.f32 " \
                 "{%0,%1,%2,%3}, {%4,%5,%6,%7}, {%8,%9}, {%0,%1,%2,%3};" \
                 : "+f"((d)[0]), "+f"((d)[1]), "+f"((d)[2]), "+f"((d)[3]) \
                 : "r"((a)[0]), "r"((a)[1]), "r"((a)[2]), "r"((a)[3]), \
                   "r"(b0), "r"(b1))

// ---------------------------------------------------------------------------
// e_scale[e] = sum_k H_e[e,k] * p[k]   (one warp per edge row)
// ---------------------------------------------------------------------------
__global__ void escale_kernel(const float* __restrict__ He,
                              const float* __restrict__ p) {
    int idx  = blockIdx.x * blockDim.x + threadIdx.x;
    int warp = idx >> 5;
    int lane = idx & 31;
    if (warp >= EE) return;
    float4 v  = reinterpret_cast<const float4*>(He + (size_t)warp * INE)[lane];
    float4 pv = reinterpret_cast<const float4*>(p)[lane];
    float s = v.x * pv.x + v.y * pv.y + v.z * pv.z + v.w * pv.w;
#pragma unroll
    for (int o = 16; o; o >>= 1) s += __shfl_xor_sync(0xFFFFFFFFu, s, o);
    if (lane == 0) g_escale[warp] = s;
}

// ---------------------------------------------------------------------------
// Split T into bf16 hi/lo:  g_A16 row = [hi(T*s) | lo(T*s)], g_B16 = [hi(T) | lo(T)]
// ---------------------------------------------------------------------------
__device__ __forceinline__ void bf16_split(float x, uint16_t& h, uint16_t& l) {
    __nv_bfloat16 hb = __float2bfloat16_rn(x);
    __nv_bfloat16 lb = __float2bfloat16_rn(x - __bfloat162float(hb));
    h = __bfloat16_as_ushort(hb);
    l = __bfloat16_as_ushort(lb);
}

__global__ void convert_kernel(const float* __restrict__ Tm) {
    size_t v = (size_t)blockIdx.x * blockDim.x + threadIdx.x;
    size_t e = v << 2;                  // 4 elements per thread
    int k = (int)(e & (EE - 1));
    int r = (int)(e >> 13);
    float4 x  = *reinterpret_cast<const float4*>(Tm + e);
    float4 sv = *reinterpret_cast<const float4*>(g_escale + k);
    float xa[4] = {x.x * sv.x, x.y * sv.y, x.z * sv.z, x.w * sv.w};
    float xb[4] = {x.x, x.y, x.z, x.w};
    uint16_t ah[4], al[4], bh[4], bl[4];
#pragma unroll
    for (int j = 0; j < 4; ++j) {
        bf16_split(xa[j], ah[j], al[j]);
        bf16_split(xb[j], bh[j], bl[j]);
    }
    __nv_bfloat16* Ar = g_A16 + (size_t)r * (2 * EE);
    __nv_bfloat16* Br = g_B16 + (size_t)r * (2 * EE);
    uint2 u;
    u.x = (uint32_t)ah[0] | ((uint32_t)ah[1] << 16);
    u.y = (uint32_t)ah[2] | ((uint32_t)ah[3] << 16);
    *reinterpret_cast<uint2*>(Ar + k) = u;
    u.x = (uint32_t)al[0] | ((uint32_t)al[1] << 16);
    u.y = (uint32_t)al[2] | ((uint32_t)al[3] << 16);
    *reinterpret_cast<uint2*>(Ar + EE + k) = u;
    u.x = (uint32_t)bh[0] | ((uint32_t)bh[1] << 16);
    u.y = (uint32_t)bh[2] | ((uint32_t)bh[3] << 16);
    *reinterpret_cast<uint2*>(Br + k) = u;
    u.x = (uint32_t)bl[0] | ((uint32_t)bl[1] << 16);
    u.y = (uint32_t)bl[2] | ((uint32_t)bl[3] << 16);
    *reinterpret_cast<uint2*>(Br + EE + k) = u;
}

// ---------------------------------------------------------------------------
// HMMA symmetric GEMM (3-pass hi/lo schedule) + fused epilogue:
//   M = Ah Bh^T + Ah Bl^T + Al Bh^T   (~= T diag(s) T^T)
//   g_C[i,j] = (i==j) ? adj_v[i,i] : 0.5*(M[i,j]+1)*adj_v[i,j]   (+ mirror)
// One CTA per triangular 128x128 tile. KC=64 bf16 (128B rows), double-buffered
// cp.async. 8 warps: 4(m) x 2(n), each 32x64 via m16n8k16.
// ---------------------------------------------------------------------------
#define NCH 384                      // 3 passes x 128 chunks
#define ROWB 32768                   // bytes per g_A16/g_B16 row (16384 bf16)
#define STAGE_BYTES 32768            // A tile 16KB + B tile 16KB
#define SMEM_SYM 66048               // max(2*STAGE_BYTES, 128*129*4)

__global__ __launch_bounds__(256, 2)
void symgemm_mma(const float* __restrict__ adjv) {
    extern __shared__ char sm[];
    const uint32_t sb = smem_u32(sm);
    const int tid = threadIdx.x, lane = tid & 31, wid = tid >> 5;
    const int wm = wid >> 1, wn = wid & 1;

    // triangular tile map: t = bj*(bj+1)/2 + bi, bi <= bj
    int t = blockIdx.x;
    int bj = (int)((sqrtf(8.0f * (float)t + 1.0f) - 1.0f) * 0.5f);
    while ((bj + 1) * (bj + 2) / 2 <= t) ++bj;
    while (bj * (bj + 1) / 2 > t) --bj;
    int bi = t - bj * (bj + 1) / 2;

    const char* Abase = (const char*)g_A16 + (size_t)(bi * 128) * ROWB;
    const char* Bbase = (const char*)g_B16 + (size_t)(bj * 128) * ROWB;

    float acc[2][8][4];
#pragma unroll
    for (int i = 0; i < 2; ++i)
#pragma unroll
        for (int j = 0; j < 8; ++j)
#pragma unroll
            for (int q = 0; q < 4; ++q) acc[i][j][q] = 0.0f;

    const int ldr = tid >> 3;            // 0..31 (row base for loads)
    const int ldk = (tid & 7) * 16;      // 0..112 (byte col within 128B)

    auto load_stage = [&](int s, int c) {
        const int p = c >> 7, cc = c & 127;
        const int kaoff = ((p == 2) ? (ROWB / 2) : 0) + cc * 128;   // A: lo on pass 2
        const int kboff = ((p == 1) ? (ROWB / 2) : 0) + cc * 128;   // B: lo on pass 1
        const uint32_t sa  = sb + s * STAGE_BYTES;
        const uint32_t sbf = sa + 16384;
#pragma unroll
        for (int i = 0; i < 4; ++i) {
            const int r = ldr + i * 32;
            const uint32_t so = SWZ((uint32_t)(r * 128 + ldk));
            CP_ASYNC16(sa  + so, Abase + (size_t)r * ROWB + kaoff + ldk);
            CP_ASYNC16(sbf + so, Bbase + (size_t)r * ROWB + kboff + ldk);
        }
        CP_COMMIT();
    };

    load_stage(0, 0);

    for (int c = 0; c < NCH; ++c) {
        const int s = c & 1;
        if (c + 1 < NCH) { load_stage(s ^ 1, c + 1); CP_WAIT(1); }
        else             { CP_WAIT(0); }
        __syncthreads();

        const uint32_t sa  = sb + s * STAGE_BYTES;
        const uint32_t sbf = sa + 16384;
#pragma unroll
        for (int ks = 0; ks < 4; ++ks) {
            uint32_t a[2][4];
#pragma unroll
            for (int mt = 0; mt < 2; ++mt) {
                const int row = wm * 32 + mt * 16 + (lane & 15);
                const int kb  = ks * 32 + ((lane >> 4) * 16);
                LDSM_X4(a[mt][0], a[mt][1], a[mt][2], a[mt][3],
                        sa + SWZ((uint32_t)(row * 128 + kb)));
            }
            uint32_t b[4][4];
#pragma unroll
            for (int ng = 0; ng < 4; ++ng) {
                const int nrow = wn * 64 + ng * 16 + ((lane >> 4) * 8) + (lane & 7);
                const int kb   = ks * 32 + (((lane >> 3) & 1) * 16);
                LDSM_X4(b[ng][0], b[ng][1], b[ng][2], b[ng][3],
                        sbf + SWZ((uint32_t)(nrow * 128 + kb)));
            }
#pragma unroll
            for (int mt = 0; mt < 2; ++mt)
#pragma unroll
                for (int ng = 0; ng < 4; ++ng) {
                    MMA16816(acc[mt][2 * ng],     a[mt], b[ng][0], b[ng][1]);
                    MMA16816(acc[mt][2 * ng + 1], a[mt], b[ng][2], b[ng][3]);
                }
        }
        __syncthreads();
    }

    // epilogue: regs -> padded SMEM -> coalesced fused global writes
    float* Msm = reinterpret_cast<float*>(sm);   // [128][129]
#pragma unroll
    for (int mt = 0; mt < 2; ++mt) {
        const int m = wm * 32 + mt * 16 + (lane >> 2);
#pragma unroll
        for (int nt = 0; nt < 8; ++nt) {
            const int n = wn * 64 + nt * 8 + 2 * (lane & 3);
            Msm[m * 129 + n]           = acc[mt][nt][0];
            Msm[m * 129 + n + 1]       = acc[mt][nt][1];
            Msm[(m + 8) * 129 + n]     = acc[mt][nt][2];
            Msm[(m + 8) * 129 + n + 1] = acc[mt][nt][3];
        }
    }
    __syncthreads();

    const int i0 = bi * 128, j0 = bj * 128;
    for (int idx = tid; idx < 128 * 128; idx += 256) {
        const int r = idx >> 7, cc = idx & 127;
        const int i = i0 + r, j = j0 + cc;
        const float Mv = 0.5f * (Msm[r * 129 + cc] + 1.0f);
        g_C[(size_t)i * NN + j] =
            (i == j) ? adjv[(size_t)i * NN + i] : Mv * adjv[(size_t)i * NN + j];
    }
    if (bi != bj) {
        for (int idx = tid; idx < 128 * 128; idx += 256) {
            const int cc = idx >> 7, r = idx & 127;
            const int i = i0 + r, j = j0 + cc;
            const float Mv = 0.5f * (Msm[r * 129 + cc] + 1.0f);
            g_C[(size_t)j * NN + i] = Mv * adjv[(size_t)j * NN + i];
        }
    }
}

// ---------------------------------------------------------------------------
// Generic SGEMM: Out[M, ldn] = A[M, K] @ B[K, ldn] (+ bias[ldn] if non-null)
// ---------------------------------------------------------------------------
#define BM 128
#define BN 128
#define BK 16
#define TM 8
#define TN 8

__global__ __launch_bounds__(256, 2)
void sgemm_kernel(const float* __restrict__ A, const float* __restrict__ B,
                  float* __restrict__ Out, const float* __restrict__ bias,
                  int K, int ldn) {
    __shared__ float As[BK][BM];
    __shared__ float Bs[BK][BN];

    const int tid  = threadIdx.x;
    const int tx   = tid & 15;
    const int ty   = tid >> 4;
    const int lrow = tid >> 2;
    const int lcol = (tid & 3) << 2;
    const int brow = tid >> 5;
    const int bcol = (tid & 31) << 2;

    const float* Aptr = A + (size_t)(blockIdx.y * BM + lrow) * K + lcol;
    const float* Bptr = B + (size_t)brow * ldn + blockIdx.x * BN + bcol;

    float acc[TM][TN] = {};

    for (int k0 = 0; k0 < K; k0 += BK) {
#pragma unroll
        for (int r = 0; r < 2; r++) {
            float4 a = *reinterpret_cast<const float4*>(Aptr + (size_t)(r * 64) * K + k0);
            int row = lrow + r * 64;
            As[lcol + 0][row] = a.x;
            As[lcol + 1][row] = a.y;
            As[lcol + 2][row] = a.z;
            As[lcol + 3][row] = a.w;
            float4 bv = *reinterpret_cast<const float4*>(Bptr + (size_t)(k0 + r * 8) * ldn);
            *reinterpret_cast<float4*>(&Bs[brow + r * 8][bcol]) = bv;
        }
        __syncthreads();
#pragma unroll
        for (int k = 0; k < BK; k++) {
            float4 a0 = *reinterpret_cast<const float4*>(&As[k][ty * TM]);
            float4 a1 = *reinterpret_cast<const float4*>(&As[k][ty * TM + 4]);
            float4 b0 = *reinterpret_cast<const float4*>(&Bs[k][tx * TN]);
            float4 b1 = *reinterpret_cast<const float4*>(&Bs[k][tx * TN + 4]);
            float af[8] = {a0.x, a0.y, a0.z, a0.w, a1.x, a1.y, a1.z, a1.w};
            float bf[8] = {b0.x, b0.y, b0.z, b0.w, b1.x, b1.y, b1.z, b1.w};
#pragma unroll
            for (int m = 0; m < TM; m++)
#pragma unroll
                for (int n = 0; n < TN; n++)
                    acc[m][n] += af[m] * bf[n];
        }
        __syncthreads();
    }

    const int gi0 = blockIdx.y * BM + ty * TM;
    const int gj0 = blockIdx.x * BN + tx * TN;
#pragma unroll
    for (int m = 0; m < TM; m++) {
        const int i = gi0 + m;
#pragma unroll
        for (int n = 0; n < TN; n++) {
            const int j = gj0 + n;
            float v = acc[m][n];
            if (bias) v += bias[j];
            Out[(size_t)i * ldn + j] = v;
        }
    }
}

// ---------------------------------------------------------------------------
// H_e passthrough into the second half of the output
// ---------------------------------------------------------------------------
__global__ void copy_kernel(const float* __restrict__ src, float* __restrict__ dst) {
    int i = blockIdx.x * blockDim.x + threadIdx.x;
    reinterpret_cast<float4*>(dst)[i] = reinterpret_cast<const float4*>(src)[i];
}

// ---------------------------------------------------------------------------
extern "C" void kernel_launch(void* const* d_in, const int* in_sizes, int n_in,
                              void* d_out, int out_size) {
    const float* Hv   = (const float*)d_in[0];
    const float* He   = (const float*)d_in[1];
    const float* adjv = (const float*)d_in[3];
    const float* Tm   = (const float*)d_in[4];
    const float* W    = (const float*)d_in[5];
    const float* p    = (const float*)d_in[6];
    const float* bias = (const float*)d_in[7];
    float* out = (float*)d_out;

    float *pC = nullptr, *pX = nullptr;
    cudaGetSymbolAddress((void**)&pC, g_C);
    cudaGetSymbolAddress((void**)&pX, g_X);

    cudaFuncSetAttribute(symgemm_mma, cudaFuncAttributeMaxDynamicSharedMemorySize, SMEM_SYM);

    // 1) e_scale = H_e @ p^T
    escale_kernel<<<(EE * 32) / 256, 256>>>(He, p);

    // 2) bf16 hi/lo split of T (scaled and unscaled)
    convert_kernel<<<(int)(((size_t)NN * EE / 4) / 256), 256>>>(Tm);

    // 3) g_C = 0.5*(T diag(s) T^T + 1) * adj_v via HMMA, symmetric tiles
    symgemm_mma<<<(NN / 128) * (NN / 128 + 1) / 2, 256, SMEM_SYM>>>(adjv);

    // 4) g_X = g_C @ H_v
    sgemm_kernel<<<dim3(INV / BN, NN / BM), 256>>>(pC, Hv, pX, nullptr, NN, INV);

    // 5) ret = g_X @ W + bias
    sgemm_kernel<<<dim3(OUTV / BN, NN / BM), 256>>>(pX, W, out, bias, INV, OUTV);

    // 6) append H_e
    copy_kernel<<<(EE * INE / 4) / 256, 256>>>(He, out + (size_t)NN * OUTV);
}

// round 7
// speedup vs baseline: 3.1039x; 1.3038x over previous
#include <cuda_runtime.h>
#include <cuda_bf16.h>
#include <cstdint>

// Problem dims (fixed by the dataset)
#define NN   4096   // nodes
#define EE   8192   // edges
#define INV  512
#define OUTV 512
#define INE  128

// Scratch (allocation-free rule: __device__ globals)
__device__ float g_escale[EE];
// bf16 hi/lo split of T rows: [hi 8192 | lo 8192] per row
__device__ __nv_bfloat16 g_A16[(size_t)NN * 2 * EE];   // 128 MB (scaled by e_scale)
__device__ __nv_bfloat16 g_B16[(size_t)NN * 2 * EE];   // 128 MB (unscaled)
__device__ __nv_bfloat16 g_Chi[(size_t)NN * NN];       // 32 MB
__device__ __nv_bfloat16 g_Clo[(size_t)NN * NN];       // 32 MB
__device__ float g_Hw[(size_t)NN * OUTV];              // 8 MB: Hv @ W
__device__ __nv_bfloat16 g_HwTh[(size_t)OUTV * NN];    // 4 MB: transposed split
__device__ __nv_bfloat16 g_HwTl[(size_t)OUTV * NN];    // 4 MB

// ============================================================================
// sm_80+ PTX helpers (NO arch-specific 'a' features — target is plain sm_103)
// ============================================================================
__device__ __forceinline__ uint32_t smem_u32(const void* p) {
    uint32_t a;
    asm("{ .reg .u64 t; cvta.to.shared.u64 t, %1; cvt.u32.u64 %0, t; }" : "=r"(a) : "l"(p));
    return a;
}

#define SWZ(o) ((o) ^ (((o) >> 3) & 0x70))

#define CP_ASYNC16(saddr, gptr) \
    asm volatile("cp.async.cg.shared.global [%0], [%1], 16;" \
                 :: "r"(saddr), "l"((size_t)__cvta_generic_to_global((const void*)(gptr))))
#define CP_COMMIT() asm volatile("cp.async.commit_group;" ::: "memory")
#define CP_WAIT(n)  asm volatile("cp.async.wait_group " #n ";" ::: "memory")

#define LDSM_X4(r0, r1, r2, r3, addr) \
    asm volatile("ldmatrix.sync.aligned.m8n8.x4.shared.b16 {%0,%1,%2,%3}, [%4];" \
                 : "=r"(r0), "=r"(r1), "=r"(r2), "=r"(r3) : "r"(addr))

#define MMA16816(d, a, b0, b1) \
    asm volatile("mma.sync.aligned.m16n8k16.row.col.f32.bf16.bf16.f32 " \
                 "{%0,%1,%2,%3}, {%4,%5,%6,%7}, {%8,%9}, {%0,%1,%2,%3};" \
                 : "+f"((d)[0]), "+f"((d)[1]), "+f"((d)[2]), "+f"((d)[3]) \
                 : "r"((a)[0]), "r"((a)[1]), "r"((a)[2]), "r"((a)[3]), \
                   "r"(b0), "r"(b1))

__device__ __forceinline__ void bf16_split(float x, uint16_t& h, uint16_t& l) {
    __nv_bfloat16 hb = __float2bfloat16_rn(x);
    __nv_bfloat16 lb = __float2bfloat16_rn(x - __bfloat162float(hb));
    h = __bfloat16_as_ushort(hb);
    l = __bfloat16_as_ushort(lb);
}

// ============================================================================
// Shared 128x128 HMMA tile machinery: 8 warps as 4(m) x 2(n), warp = 32x64.
// SMEM tile layout: 128 rows x 128B (64 bf16), SW128 swizzled.
// ============================================================================
__device__ __forceinline__ void lds_afrag(uint32_t base, int wm, int lane, int ks,
                                          uint32_t a[2][4]) {
#pragma unroll
    for (int mt = 0; mt < 2; ++mt) {
        const int row = wm * 32 + mt * 16 + (lane & 15);
        const int kb  = ks * 32 + ((lane >> 4) * 16);
        LDSM_X4(a[mt][0], a[mt][1], a[mt][2], a[mt][3],
                base + SWZ((uint32_t)(row * 128 + kb)));
    }
}

__device__ __forceinline__ void lds_bfrag(uint32_t base, int wn, int lane, int ks,
                                          uint32_t b[4][4]) {
#pragma unroll
    for (int ng = 0; ng < 4; ++ng) {
        const int nrow = wn * 64 + ng * 16 + ((lane >> 4) * 8) + (lane & 7);
        const int kb   = ks * 32 + (((lane >> 3) & 1) * 16);
        LDSM_X4(b[ng][0], b[ng][1], b[ng][2], b[ng][3],
                base + SWZ((uint32_t)(nrow * 128 + kb)));
    }
}

__device__ __forceinline__ void mma_block(float acc[2][8][4],
                                          uint32_t a[2][4], uint32_t b[4][4]) {
#pragma unroll
    for (int mt = 0; mt < 2; ++mt)
#pragma unroll
        for (int ng = 0; ng < 4; ++ng) {
            MMA16816(acc[mt][2 * ng],     a[mt], b[ng][0], b[ng][1]);
            MMA16816(acc[mt][2 * ng + 1], a[mt], b[ng][2], b[ng][3]);
        }
}

// load one 16KB tile (128 rows x 128B) via cp.async; caller commits the group
__device__ __forceinline__ void load_tile(uint32_t sdst, const char* gsrc,
                                          size_t row_stride, int ldr, int ldk) {
#pragma unroll
    for (int i = 0; i < 4; ++i) {
        const int r = ldr + i * 32;
        CP_ASYNC16(sdst + SWZ((uint32_t)(r * 128 + ldk)),
                   gsrc + (size_t)r * row_stride + ldk);
    }
}

// ---------------------------------------------------------------------------
// e_scale[e] = sum_k H_e[e,k] * p[k]
// ---------------------------------------------------------------------------
__global__ void escale_kernel(const float* __restrict__ He,
                              const float* __restrict__ p) {
    int idx  = blockIdx.x * blockDim.x + threadIdx.x;
    int warp = idx >> 5;
    int lane = idx & 31;
    if (warp >= EE) return;
    float4 v  = reinterpret_cast<const float4*>(He + (size_t)warp * INE)[lane];
    float4 pv = reinterpret_cast<const float4*>(p)[lane];
    float s = v.x * pv.x + v.y * pv.y + v.z * pv.z + v.w * pv.w;
#pragma unroll
    for (int o = 16; o; o >>= 1) s += __shfl_xor_sync(0xFFFFFFFFu, s, o);
    if (lane == 0) g_escale[warp] = s;
}

// ---------------------------------------------------------------------------
// Split T into bf16 hi/lo: g_A16 row = [hi(T*s)|lo(T*s)], g_B16 = [hi(T)|lo(T)]
// ---------------------------------------------------------------------------
__global__ void convert_kernel(const float* __restrict__ Tm) {
    size_t v = (size_t)blockIdx.x * blockDim.x + threadIdx.x;
    size_t e = v << 2;
    int k = (int)(e & (EE - 1));
    int r = (int)(e >> 13);
    float4 x  = *reinterpret_cast<const float4*>(Tm + e);
    float4 sv = *reinterpret_cast<const float4*>(g_escale + k);
    float xa[4] = {x.x * sv.x, x.y * sv.y, x.z * sv.z, x.w * sv.w};
    float xb[4] = {x.x, x.y, x.z, x.w};
    uint16_t ah[4], al[4], bh[4], bl[4];
#pragma unroll
    for (int j = 0; j < 4; ++j) {
        bf16_split(xa[j], ah[j], al[j]);
        bf16_split(xb[j], bh[j], bl[j]);
    }
    __nv_bfloat16* Ar = g_A16 + (size_t)r * (2 * EE);
    __nv_bfloat16* Br = g_B16 + (size_t)r * (2 * EE);
    uint2 u;
    u.x = (uint32_t)ah[0] | ((uint32_t)ah[1] << 16);
    u.y = (uint32_t)ah[2] | ((uint32_t)ah[3] << 16);
    *reinterpret_cast<uint2*>(Ar + k) = u;
    u.x = (uint32_t)al[0] | ((uint32_t)al[1] << 16);
    u.y = (uint32_t)al[2] | ((uint32_t)al[3] << 16);
    *reinterpret_cast<uint2*>(Ar + EE + k) = u;
    u.x = (uint32_t)bh[0] | ((uint32_t)bh[1] << 16);
    u.y = (uint32_t)bh[2] | ((uint32_t)bh[3] << 16);
    *reinterpret_cast<uint2*>(Br + k) = u;
    u.x = (uint32_t)bl[0] | ((uint32_t)bl[1] << 16);
    u.y = (uint32_t)bl[2] | ((uint32_t)bl[3] << 16);
    *reinterpret_cast<uint2*>(Br + EE + k) = u;
}

// ---------------------------------------------------------------------------
// Transpose-split Hw [4096,512] -> g_HwTh/g_HwTl [512][4096]
// ---------------------------------------------------------------------------
__global__ void transpose_split_kernel(const float* __restrict__ Hw) {
    __shared__ float tile[32][33];
    const int n0 = blockIdx.x * 32, j0 = blockIdx.y * 32;
    const int tx = threadIdx.x, ty = threadIdx.y;   // 32 x 8
#pragma unroll
    for (int i = 0; i < 4; ++i)
        tile[ty + 8 * i][tx] = Hw[(size_t)(j0 + ty + 8 * i) * OUTV + n0 + tx];
    __syncthreads();
#pragma unroll
    for (int i = 0; i < 4; ++i) {
        const int n = n0 + ty + 8 * i, j = j0 + tx;
        float v = tile[tx][ty + 8 * i];
        uint16_t h, l;
        bf16_split(v, h, l);
        g_HwTh[(size_t)n * NN + j] = __ushort_as_bfloat16(h);
        g_HwTl[(size_t)n * NN + j] = __ushort_as_bfloat16(l);
    }
}

// ---------------------------------------------------------------------------
// HMMA symmetric GEMM, chunk-major hi/lo: per K-chunk load Ah,Al,Bh,Bl (64KB),
// run 3 combos (AhBh + AhBl + AlBh). Fused epilogue writes split C:
//   Cv[i,j] = (i==j) ? adj_v[i,i] : 0.5*(M[i,j]+1)*adj_v[i,j]  (+ mirror)
// ---------------------------------------------------------------------------
#define ROWB 32768                   // bytes per g_A16/g_B16 row
#define STG  65536                   // stage: Ah|Al|Bh|Bl x 16KB
#define SMEM_SYM (2 * STG)           // 128 KB

__global__ __launch_bounds__(256, 1)
void symgemm_mma(const float* __restrict__ adjv) {
    extern __shared__ char sm[];
    const uint32_t sb = smem_u32(sm);
    const int tid = threadIdx.x, lane = tid & 31, wid = tid >> 5;
    const int wm = wid >> 1, wn = wid & 1;

    int t = blockIdx.x;
    int bj = (int)((sqrtf(8.0f * (float)t + 1.0f) - 1.0f) * 0.5f);
    while ((bj + 1) * (bj + 2) / 2 <= t) ++bj;
    while (bj * (bj + 1) / 2 > t) --bj;
    int bi = t - bj * (bj + 1) / 2;

    const char* Abase = (const char*)g_A16 + (size_t)(bi * 128) * ROWB;
    const char* Bbase = (const char*)g_B16 + (size_t)(bj * 128) * ROWB;

    float acc[2][8][4];
#pragma unroll
    for (int i = 0; i < 2; ++i)
#pragma unroll
        for (int j = 0; j < 8; ++j)
#pragma unroll
            for (int q = 0; q < 4; ++q) acc[i][j][q] = 0.0f;

    const int ldr = tid >> 3;
    const int ldk = (tid & 7) * 16;

    auto load_stage = [&](int s, int c) {
        const uint32_t st = sb + s * STG;
        const int kb = c * 128;                 // byte offset of chunk in hi half
        load_tile(st,             Abase + kb,             ROWB, ldr, ldk);  // Ah
        load_tile(st + 16384,     Abase + 16384 + kb,     ROWB, ldr, ldk);  // Al
        load_tile(st + 32768,     Bbase + kb,             ROWB, ldr, ldk);  // Bh
        load_tile(st + 49152,     Bbase + 16384 + kb,     ROWB, ldr, ldk);  // Bl
        CP_COMMIT();
    };

    load_stage(0, 0);

    for (int c = 0; c < 128; ++c) {
        const int s = c & 1;
        if (c + 1 < 128) { load_stage(s ^ 1, c + 1); CP_WAIT(1); }
        else             { CP_WAIT(0); }
        __syncthreads();

        const uint32_t st = sb + s * STG;
#pragma unroll
        for (int ks = 0; ks < 4; ++ks) {
            uint32_t ah[2][4], al[2][4], bh[4][4], bl[4][4];
            lds_afrag(st,         wm, lane, ks, ah);
            lds_afrag(st + 16384, wm, lane, ks, al);
            lds_bfrag(st + 32768, wn, lane, ks, bh);
            lds_bfrag(st + 49152, wn, lane, ks, bl);
            mma_block(acc, ah, bh);
            mma_block(acc, ah, bl);
            mma_block(acc, al, bh);
        }
        __syncthreads();
    }

    // epilogue: regs -> padded SMEM -> fused split-bf16 global writes
    float* Msm = reinterpret_cast<float*>(sm);   // [128][129]
#pragma unroll
    for (int mt = 0; mt < 2; ++mt) {
        const int m = wm * 32 + mt * 16 + (lane >> 2);
#pragma unroll
        for (int nt = 0; nt < 8; ++nt) {
            const int n = wn * 64 + nt * 8 + 2 * (lane & 3);
            Msm[m * 129 + n]           = acc[mt][nt][0];
            Msm[m * 129 + n + 1]       = acc[mt][nt][1];
            Msm[(m + 8) * 129 + n]     = acc[mt][nt][2];
            Msm[(m + 8) * 129 + n + 1] = acc[mt][nt][3];
        }
    }
    __syncthreads();

    const int i0 = bi * 128, j0 = bj * 128;
    // direct block: thread handles 2 consecutive j for packed 4B writes
    for (int idx = tid; idx < 128 * 64; idx += 256) {
        const int r = idx >> 6, c2 = (idx & 63) * 2;
        const int i = i0 + r, j = j0 + c2;
        float v0 = 0.5f * (Msm[r * 129 + c2] + 1.0f);
        float v1 = 0.5f * (Msm[r * 129 + c2 + 1] + 1.0f);
        v0 = (i == j)     ? adjv[(size_t)i * NN + i] : v0 * adjv[(size_t)i * NN + j];
        v1 = (i == j + 1) ? adjv[(size_t)i * NN + i] : v1 * adjv[(size_t)i * NN + j + 1];
        uint16_t h0, l0, h1, l1;
        bf16_split(v0, h0, l0);
        bf16_split(v1, h1, l1);
        const size_t o = ((size_t)i * NN + j) >> 1;
        reinterpret_cast<uint32_t*>(g_Chi)[o] = (uint32_t)h0 | ((uint32_t)h1 << 16);
        reinterpret_cast<uint32_t*>(g_Clo)[o] = (uint32_t)l0 | ((uint32_t)l1 << 16);
    }
    if (bi != bj) {
        // mirror block: thread handles 2 consecutive i
        for (int idx = tid; idx < 128 * 64; idx += 256) {
            const int cc = idx >> 6, r2 = (idx & 63) * 2;
            const int i = i0 + r2, j = j0 + cc;
            float v0 = 0.5f * (Msm[r2 * 129 + cc] + 1.0f) * adjv[(size_t)j * NN + i];
            float v1 = 0.5f * (Msm[(r2 + 1) * 129 + cc] + 1.0f) * adjv[(size_t)j * NN + i + 1];
            uint16_t h0, l0, h1, l1;
            bf16_split(v0, h0, l0);
            bf16_split(v1, h1, l1);
            const size_t o = ((size_t)j * NN + i) >> 1;
            reinterpret_cast<uint32_t*>(g_Chi)[o] = (uint32_t)h0 | ((uint32_t)h1 << 16);
            reinterpret_cast<uint32_t*>(g_Clo)[o] = (uint32_t)l0 | ((uint32_t)l1 << 16);
        }
    }
}

// ---------------------------------------------------------------------------
// Final HMMA GEMM: out[4096,512] = (Chi+Clo) @ (HwTh+HwTl)^T + bias
// 3-term split, chunk-major; A rows = g_Chi/g_Clo (8192B stride),
// B rows = g_HwTh/g_HwTl (8192B stride, n-major). K = 4096 -> 64 chunks.
// ---------------------------------------------------------------------------
__global__ __launch_bounds__(256, 1)
void final_mma(float* __restrict__ out, const float* __restrict__ bias) {
    extern __shared__ char sm[];
    const uint32_t sb = smem_u32(sm);
    const int tid = threadIdx.x, lane = tid & 31, wid = tid >> 5;
    const int wm = wid >> 1, wn = wid & 1;

    const int m0 = blockIdx.y * 128, n0 = blockIdx.x * 128;
    const char* Ah = (const char*)g_Chi  + (size_t)m0 * (NN * 2);
    const char* Al = (const char*)g_Clo  + (size_t)m0 * (NN * 2);
    const char* Bh = (const char*)g_HwTh + (size_t)n0 * (NN * 2);
    const char* Bl = (const char*)g_HwTl + (size_t)n0 * (NN * 2);

    float acc[2][8][4];
#pragma unroll
    for (int i = 0; i < 2; ++i)
#pragma unroll
        for (int j = 0; j < 8; ++j)
#pragma unroll
            for (int q = 0; q < 4; ++q) acc[i][j][q] = 0.0f;

    const int ldr = tid >> 3;
    const int ldk = (tid & 7) * 16;

    auto load_stage = [&](int s, int c) {
        const uint32_t st = sb + s * STG;
        const int kb = c * 128;
        load_tile(st,         Ah + kb, NN * 2, ldr, ldk);
        load_tile(st + 16384, Al + kb, NN * 2, ldr, ldk);
        load_tile(st + 32768, Bh + kb, NN * 2, ldr, ldk);
        load_tile(st + 49152, Bl + kb, NN * 2, ldr, ldk);
        CP_COMMIT();
    };

    load_stage(0, 0);

    for (int c = 0; c < 64; ++c) {
        const int s = c & 1;
        if (c + 1 < 64) { load_stage(s ^ 1, c + 1); CP_WAIT(1); }
        else            { CP_WAIT(0); }
        __syncthreads();

        const uint32_t st = sb + s * STG;
#pragma unroll
        for (int ks = 0; ks < 4; ++ks) {
            uint32_t ah[2][4], al[2][4], bh[4][4], bl[4][4];
            lds_afrag(st,         wm, lane, ks, ah);
            lds_afrag(st + 16384, wm, lane, ks, al);
            lds_bfrag(st + 32768, wn, lane, ks, bh);
            lds_bfrag(st + 49152, wn, lane, ks, bl);
            mma_block(acc, ah, bh);
            mma_block(acc, ah, bl);
            mma_block(acc, al, bh);
        }
        __syncthreads();
    }

    // epilogue: regs -> padded SMEM -> coalesced fp32 writes + bias
    float* Msm = reinterpret_cast<float*>(sm);   // [128][129]
#pragma unroll
    for (int mt = 0; mt < 2; ++mt) {
        const int m = wm * 32 + mt * 16 + (lane >> 2);
#pragma unroll
        for (int nt = 0; nt < 8; ++nt) {
            const int n = wn * 64 + nt * 8 + 2 * (lane & 3);
            Msm[m * 129 + n]           = acc[mt][nt][0];
            Msm[m * 129 + n + 1]       = acc[mt][nt][1];
            Msm[(m + 8) * 129 + n]     = acc[mt][nt][2];
            Msm[(m + 8) * 129 + n + 1] = acc[mt][nt][3];
        }
    }
    __syncthreads();

    for (int idx = tid; idx < 128 * 128; idx += 256) {
        const int r = idx >> 7, cc = idx & 127;
        out[(size_t)(m0 + r) * OUTV + n0 + cc] = Msm[r * 129 + cc] + bias[n0 + cc];
    }
}

// ---------------------------------------------------------------------------
// fp32 SGEMM (for the small Hw = Hv @ W): Out[M, ldn] = A[M,K] @ B[K,ldn]
// ---------------------------------------------------------------------------
#define BM 128
#define BN 128
#define BK 16
#define TM 8
#define TN 8

__global__ __launch_bounds__(256, 2)
void sgemm_kernel(const float* __restrict__ A, const float* __restrict__ B,
                  float* __restrict__ Out, int K, int ldn) {
    __shared__ float As[BK][BM];
    __shared__ float Bs[BK][BN];

    const int tid  = threadIdx.x;
    const int tx   = tid & 15;
    const int ty   = tid >> 4;
    const int lrow = tid >> 2;
    const int lcol = (tid & 3) << 2;
    const int brow = tid >> 5;
    const int bcol = (tid & 31) << 2;

    const float* Aptr = A + (size_t)(blockIdx.y * BM + lrow) * K + lcol;
    const float* Bptr = B + (size_t)brow * ldn + blockIdx.x * BN + bcol;

    float acc[TM][TN] = {};

    for (int k0 = 0; k0 < K; k0 += BK) {
#pragma unroll
        for (int r = 0; r < 2; r++) {
            float4 a = *reinterpret_cast<const float4*>(Aptr + (size_t)(r * 64) * K + k0);
            int row = lrow + r * 64;
            As[lcol + 0][row] = a.x;
            As[lcol + 1][row] = a.y;
            As[lcol + 2][row] = a.z;
            As[lcol + 3][row] = a.w;
            float4 bv = *reinterpret_cast<const float4*>(Bptr + (size_t)(k0 + r * 8) * ldn);
            *reinterpret_cast<float4*>(&Bs[brow + r * 8][bcol]) = bv;
        }
        __syncthreads();
#pragma unroll
        for (int k = 0; k < BK; k++) {
            float4 a0 = *reinterpret_cast<const float4*>(&As[k][ty * TM]);
            float4 a1 = *reinterpret_cast<const float4*>(&As[k][ty * TM + 4]);
            float4 b0 = *reinterpret_cast<const float4*>(&Bs[k][tx * TN]);
            float4 b1 = *reinterpret_cast<const float4*>(&Bs[k][tx * TN + 4]);
            float af[8] = {a0.x, a0.y, a0.z, a0.w, a1.x, a1.y, a1.z, a1.w};
            float bf[8] = {b0.x, b0.y, b0.z, b0.w, b1.x, b1.y, b1.z, b1.w};
#pragma unroll
            for (int m = 0; m < TM; m++)
#pragma unroll
                for (int n = 0; n < TN; n++)
                    acc[m][n] += af[m] * bf[n];
        }
        __syncthreads();
    }

    const int gi0 = blockIdx.y * BM + ty * TM;
    const int gj0 = blockIdx.x * BN + tx * TN;
#pragma unroll
    for (int m = 0; m < TM; m++)
#pragma unroll
        for (int n = 0; n < TN; n++)
            Out[(size_t)(gi0 + m) * ldn + gj0 + n] = acc[m][n];
}

// ---------------------------------------------------------------------------
// H_e passthrough
// ---------------------------------------------------------------------------
__global__ void copy_kernel(const float* __restrict__ src, float* __restrict__ dst) {
    int i = blockIdx.x * blockDim.x + threadIdx.x;
    reinterpret_cast<float4*>(dst)[i] = reinterpret_cast<const float4*>(src)[i];
}

// ---------------------------------------------------------------------------
extern "C" void kernel_launch(void* const* d_in, const int* in_sizes, int n_in,
                              void* d_out, int out_size) {
    const float* Hv   = (const float*)d_in[0];
    const float* He   = (const float*)d_in[1];
    const float* adjv = (const float*)d_in[3];
    const float* Tm   = (const float*)d_in[4];
    const float* W    = (const float*)d_in[5];
    const float* p    = (const float*)d_in[6];
    const float* bias = (const float*)d_in[7];
    float* out = (float*)d_out;

    float* pHw = nullptr;
    cudaGetSymbolAddress((void**)&pHw, g_Hw);

    cudaFuncSetAttribute(symgemm_mma, cudaFuncAttributeMaxDynamicSharedMemorySize, SMEM_SYM);
    cudaFuncSetAttribute(final_mma,   cudaFuncAttributeMaxDynamicSharedMemorySize, SMEM_SYM);

    // 1) e_scale = H_e @ p^T
    escale_kernel<<<(EE * 32) / 256, 256>>>(He, p);

    // 2) bf16 hi/lo split of T (scaled and unscaled)
    convert_kernel<<<(int)(((size_t)NN * EE / 4) / 256), 256>>>(Tm);

    // 3) Hw = Hv @ W  (fp32; small)
    sgemm_kernel<<<dim3(OUTV / BN, NN / BM), 256>>>(Hv, W, pHw, INV, OUTV);

    // 4) transpose + split Hw -> HwT hi/lo
    transpose_split_kernel<<<dim3(OUTV / 32, NN / 32), dim3(32, 8)>>>(pHw);

    // 5) split C = 0.5*(T diag(s) T^T + 1) * adj_v via HMMA, symmetric tiles
    symgemm_mma<<<(NN / 128) * (NN / 128 + 1) / 2, 256, SMEM_SYM>>>(adjv);

    // 6) out = C @ Hw + bias via HMMA
    final_mma<<<dim3(OUTV / 128, NN / 128), 256, SMEM_SYM>>>(out, bias);

    // 7) append H_e
    copy_kernel<<<(EE * INE / 4) / 256, 256>>>(He, out + (size_t)NN * OUTV);
}